// round 5
// baseline (speedup 1.0000x reference)
#include <cuda_runtime.h>

#define NP 262144          // 2048*128 points
#define GD3 884736         // 96^3

typedef unsigned long long u64;

__device__ __forceinline__ u64 pk2(float lo, float hi) {
    u64 r; asm("mov.b64 %0, {%1,%2};" : "=l"(r) : "f"(lo), "f"(hi)); return r;
}
__device__ __forceinline__ void upk2(u64 v, float& lo, float& hi) {
    asm("mov.b64 {%0,%1}, %2;" : "=f"(lo), "=f"(hi) : "l"(v));
}
__device__ __forceinline__ u64 ffma2(u64 a, u64 b, u64 c) {
    u64 d; asm("fma.rn.f32x2 %0, %1, %2, %3;" : "=l"(d) : "l"(a), "l"(b), "l"(c)); return d;
}

// ---------------- scratch (static device globals; allocation-free) ----------------
__device__ float g_feats[NP * 32];
__device__ float g_dfp[NP * 96];            // [P][3][32] d feat / d p
__device__ float g_H1[(size_t)NP * 256];
__device__ float g_H2[(size_t)NP * 256];
__device__ float g_geo[NP * 15];
__device__ float g_W1T[256 * 256];          // W1T[j][i] = W1[i][j]
__device__ float g_W0T[256 * 35];           // W0T[j][i] = W0[i][j]

// ---------------- weight transpose ----------------
__global__ void k_transpose(const float* __restrict__ W0, const float* __restrict__ W1) {
    int total = 256 * 256 + 256 * 35;
    for (int g = blockIdx.x * blockDim.x + threadIdx.x; g < total; g += gridDim.x * blockDim.x) {
        if (g < 65536) {
            int j = g >> 8, i = g & 255;
            g_W1T[j * 256 + i] = W1[i * 256 + j];
        } else {
            int t = g - 65536;
            int j = t / 35, i = t - j * 35;
            g_W0T[t] = W0[i * 256 + j];
        }
    }
}

// ---------------- trilinear sampling: feats + d feat/d p ----------------
__global__ void k_sample(const float* __restrict__ pts,
                         const float* __restrict__ vol0,
                         const float* __restrict__ vol1) {
    extern __shared__ float sm[];
    float* sFeat = sm;            // 64*33 (padded)
    float* sDfp  = sm + 2112;     // 64*97 (padded)
    int tid = threadIdx.x;
    int p = blockIdx.x * 64 + tid;

    float px = pts[p * 3 + 0], py = pts[p * 3 + 1], pz = pts[p * 3 + 2];
    float x = px * 95.f, y = py * 95.f, z = pz * 95.f;
    int x0 = (int)floorf(x); x0 = min(max(x0, 0), 94);
    int y0 = (int)floorf(y); y0 = min(max(y0, 0), 94);
    int z0 = (int)floorf(z); z0 = min(max(z0, 0), 94);
    float xd = x - (float)x0, yd = y - (float)y0, zd = z - (float)z0;
    float wx0 = 1.f - xd, wx1 = xd;
    float wy0 = 1.f - yd, wy1 = yd;
    float wz0 = 1.f - zd, wz1 = zd;

    int base = (z0 * 96 + y0) * 96 + x0;
    const float* vols[2] = { vol0, vol1 };

    #pragma unroll
    for (int v = 0; v < 2; v++) {
        const float* vb = vols[v] + base;
        #pragma unroll 4
        for (int c = 0; c < 16; c++) {
            const float* q = vb + c * GD3;
            float v000 = __ldg(q);        float v001 = __ldg(q + 1);
            float v010 = __ldg(q + 96);   float v011 = __ldg(q + 97);
            float v100 = __ldg(q + 9216); float v101 = __ldg(q + 9217);
            float v110 = __ldg(q + 9312); float v111 = __ldg(q + 9313);
            float feat = wz0 * (wy0 * (v000 * wx0 + v001 * wx1) + wy1 * (v010 * wx0 + v011 * wx1))
                       + wz1 * (wy0 * (v100 * wx0 + v101 * wx1) + wy1 * (v110 * wx0 + v111 * wx1));
            float dfx = 95.f * (wz0 * (wy0 * (v001 - v000) + wy1 * (v011 - v010))
                              + wz1 * (wy0 * (v101 - v100) + wy1 * (v111 - v110)));
            float dfy = 95.f * (wz0 * (wx0 * (v010 - v000) + wx1 * (v011 - v001))
                              + wz1 * (wx0 * (v110 - v100) + wx1 * (v111 - v101)));
            float dfz = 95.f * (wy0 * (wx0 * (v100 - v000) + wx1 * (v101 - v001))
                              + wy1 * (wx0 * (v110 - v010) + wx1 * (v111 - v011)));
            // feature permutation: [f0 c0..7 | f1 c0..7 | f0 c8..15 | f1 c8..15]
            int fi = (c >> 3) * 16 + v * 8 + (c & 7);
            sFeat[tid * 33 + fi] = feat;
            sDfp[tid * 97 + fi]      = dfx;
            sDfp[tid * 97 + 32 + fi] = dfy;
            sDfp[tid * 97 + 64 + fi] = dfz;
        }
    }
    __syncthreads();
    int fb = blockIdx.x * 64 * 32;
    for (int t = tid; t < 2048; t += 64)
        g_feats[fb + t] = sFeat[(t >> 5) * 33 + (t & 31)];
    int db = blockIdx.x * 64 * 96;
    for (int t = tid; t < 6144; t += 64) {
        int pp = t / 96, q = t - pp * 96;
        g_dfp[db + t] = sDfp[pp * 97 + q];
    }
}

// ---------------- 64-point x 256-out tile GEMM ----------------
// lane owns column pairs (2*lane + 64*jj, +1), jj = 0..3  -> conflict-free LDS.64
// pairs are contiguous -> fma.rn.f32x2 on real packed operands
__device__ __forceinline__ void gemm64x256(
    const float* sA, int lda, const float* __restrict__ gW, int KD,
    const float* __restrict__ gBias, float* sOut, float* sW,
    bool do_relu, float* gOut, const float* gMask)
{
    int tid = threadIdx.x;
    int p0 = (tid >> 5) * 8;       // warp -> 8 points
    int lane = tid & 31;
    int jc0 = 2 * lane;            // base column (pairs at jc0 + 64*jj)
    u64 acc[8][4];
    u64 binit[4];
    #pragma unroll
    for (int jp = 0; jp < 4; jp++)
        binit[jp] = gBias ? *(const u64*)(gBias + jc0 + 64 * jp) : 0ull;
    #pragma unroll
    for (int i = 0; i < 8; i++)
        #pragma unroll
        for (int jp = 0; jp < 4; jp++) acc[i][jp] = binit[jp];

    for (int k0 = 0; k0 < KD; k0 += 32) {
        int kc = KD - k0; if (kc > 32) kc = 32;
        __syncthreads();
        for (int t = tid; t < kc * 64; t += 256) {
            int r = t >> 6, c = t & 63;
            ((float4*)sW)[r * 64 + c] = ((const float4*)(gW + (size_t)(k0 + r) * 256))[c];
        }
        __syncthreads();
        if (kc == 32) {
            #pragma unroll
            for (int k = 0; k < 32; k++) {
                u64 a2[8];
                #pragma unroll
                for (int i = 0; i < 8; i++) {
                    float av = sA[(p0 + i) * lda + k0 + k];
                    a2[i] = pk2(av, av);
                }
                const u64* wp = (const u64*)(sW + k * 256) + lane;
                u64 w2[4] = { wp[0], wp[32], wp[64], wp[96] };
                #pragma unroll
                for (int i = 0; i < 8; i++)
                    #pragma unroll
                    for (int jp = 0; jp < 4; jp++)
                        acc[i][jp] = ffma2(a2[i], w2[jp], acc[i][jp]);
            }
        } else {
            for (int k = 0; k < kc; k++) {
                u64 a2[8];
                #pragma unroll
                for (int i = 0; i < 8; i++) {
                    float av = sA[(p0 + i) * lda + k0 + k];
                    a2[i] = pk2(av, av);
                }
                const u64* wp = (const u64*)(sW + k * 256) + lane;
                u64 w2[4] = { wp[0], wp[32], wp[64], wp[96] };
                #pragma unroll
                for (int i = 0; i < 8; i++)
                    #pragma unroll
                    for (int jp = 0; jp < 4; jp++)
                        acc[i][jp] = ffma2(a2[i], w2[jp], acc[i][jp]);
            }
        }
    }
    #pragma unroll
    for (int i = 0; i < 8; i++) {
        #pragma unroll
        for (int jp = 0; jp < 4; jp++) {
            float lo, hi; upk2(acc[i][jp], lo, hi);
            if (do_relu) { lo = fmaxf(lo, 0.f); hi = fmaxf(hi, 0.f); }
            if (gMask) {
                const float* mp = gMask + (size_t)(p0 + i) * 256 + jc0 + 64 * jp;
                float m0 = mp[0], m1 = mp[1];
                lo = (m0 > 0.f) ? lo : 0.f;
                hi = (m1 > 0.f) ? hi : 0.f;
            }
            u64 packed = pk2(lo, hi);
            *(u64*)(sOut + (p0 + i) * 256 + jc0 + 64 * jp) = packed;
            if (gOut)
                *(u64*)(gOut + (size_t)(p0 + i) * 256 + jc0 + 64 * jp) = packed;
        }
    }
    __syncthreads();
}

// ---------------- forward MLP ----------------
__global__ __launch_bounds__(256) void k_forward(
    const float* __restrict__ pts,
    const float* __restrict__ W0, const float* __restrict__ b0,
    const float* __restrict__ W1, const float* __restrict__ b1,
    const float* __restrict__ W2, const float* __restrict__ b2,
    float* __restrict__ out)
{
    extern __shared__ float sm[];
    float* sW  = sm;             // 8192
    float* sH1 = sm + 8192;      // 16384
    float* sH2 = sm + 24576;     // 16384
    float* sX  = sm + 40960;     // 64*36
    int tid = threadIdx.x;
    int pb = blockIdx.x * 64;

    for (int t = tid; t < 192; t += 256) { int p = t / 3, a = t - p * 3; sX[p * 36 + a] = pts[(pb + p) * 3 + a]; }
    for (int t = tid; t < 2048; t += 256) { int p = t >> 5, c = t & 31; sX[p * 36 + 3 + c] = g_feats[pb * 32 + t]; }
    __syncthreads();

    gemm64x256(sX, 36, W0, 35, b0, sH1, sW, true, g_H1 + (size_t)pb * 256, nullptr);
    gemm64x256(sH1, 256, W1, 256, b1, sH2, sW, true, g_H2 + (size_t)pb * 256, nullptr);

    // layer 3: 256 -> 16  (W2 staged in sW), packed along k
    for (int t = tid; t < 1024; t += 256) ((float4*)sW)[t] = ((const float4*)W2)[t];
    __syncthreads();
    int jc = tid & 15, pr = tid >> 4;
    u64 acc2[4];
    float bb = b2[jc];
    #pragma unroll
    for (int i = 0; i < 4; i++) acc2[i] = pk2(bb, 0.f);
    for (int k = 0; k < 256; k += 2) {
        u64 w2 = pk2(sW[k * 16 + jc], sW[k * 16 + 16 + jc]);
        #pragma unroll
        for (int i = 0; i < 4; i++)
            acc2[i] = ffma2(*(const u64*)(sH2 + (pr * 4 + i) * 256 + k), w2, acc2[i]);
    }
    #pragma unroll
    for (int i = 0; i < 4; i++) {
        float lo, hi; upk2(acc2[i], lo, hi);
        float a = lo + hi;
        int pt = pb + pr * 4 + i;
        if (jc == 0) out[(size_t)NP * 4 + pt] = a;
        else         g_geo[pt * 15 + jc - 1] = a;
    }
}

// ---------------- backward: gradients of sdf wrt points ----------------
__global__ __launch_bounds__(256) void k_backward(
    const float* __restrict__ W2, float* __restrict__ out)
{
    extern __shared__ float sm[];
    float* sW   = sm;            // 8960 (k-chunk / W0T)
    float* sG2  = sm + 8960;     // 16384
    float* sG1  = sm + 25344;    // 16384
    float* sGx  = sm + 41728;    // 2240
    float* sDfp = sm + 43968;    // 6144
    float* sB   = sm + 50112;    // 256
    int tid = threadIdx.x;
    int pb = blockIdx.x * 64;

    sB[tid] = W2[tid * 16];      // W2 column 0
    __syncthreads();

    const float4* h2 = (const float4*)(g_H2 + (size_t)pb * 256);
    for (int t = tid; t < 4096; t += 256) {
        float4 h = h2[t];
        int j = (t & 63) * 4;
        float4 g;
        g.x = h.x > 0.f ? sB[j]     : 0.f;
        g.y = h.y > 0.f ? sB[j + 1] : 0.f;
        g.z = h.z > 0.f ? sB[j + 2] : 0.f;
        g.w = h.w > 0.f ? sB[j + 3] : 0.f;
        ((float4*)sG2)[t] = g;
    }
    // G1 = (G2 @ W1^T) * (H1 > 0)
    gemm64x256(sG2, 256, g_W1T, 256, nullptr, sG1, sW, false, nullptr, g_H1 + (size_t)pb * 256);

    // Gx = G1 @ W0^T  (N = 35), packed along k
    for (int t = tid; t < 2240; t += 256) ((float4*)sW)[t] = ((const float4*)g_W0T)[t];
    for (int t = tid; t < 6144; t += 256) sDfp[t] = g_dfp[(size_t)pb * 96 + t];
    __syncthreads();
    for (int o = tid; o < 2240; o += 256) {
        int p = o / 35, i = o - p * 35;
        u64 a2 = 0ull;
        const float* gr = sG1 + p * 256;
        for (int k = 0; k < 256; k += 2)
            a2 = ffma2(*(const u64*)(gr + k), pk2(sW[k * 35 + i], sW[k * 35 + 35 + i]), a2);
        float lo, hi; upk2(a2, lo, hi);
        sGx[o] = lo + hi;
    }
    __syncthreads();
    if (tid < 64) {
        int p = tid, pt = pb + p;
        float gx = sGx[p * 35], gy = sGx[p * 35 + 1], gz = sGx[p * 35 + 2];
        #pragma unroll
        for (int c = 0; c < 32; c++) {
            float q = sGx[p * 35 + 3 + c];
            gx = fmaf(q, sDfp[p * 96 + c],      gx);
            gy = fmaf(q, sDfp[p * 96 + 32 + c], gy);
            gz = fmaf(q, sDfp[p * 96 + 64 + c], gz);
        }
        out[(size_t)NP * 5 + pt * 3 + 0] = gx;
        out[(size_t)NP * 5 + pt * 3 + 1] = gy;
        out[(size_t)NP * 5 + pt * 3 + 2] = gz;
        float n = sqrtf(gx * gx + gy * gy + gz * gz);
        float inv = 1.f / fmaxf(n, 1e-12f);
        out[(size_t)NP * 8 + pt * 3 + 0] = gx * inv;
        out[(size_t)NP * 8 + pt * 3 + 1] = gy * inv;
        out[(size_t)NP * 8 + pt * 3 + 2] = gz * inv;
    }
}

// ---------------- RGB head + elementwise outputs ----------------
__global__ __launch_bounds__(256) void k_rgb(
    const float* __restrict__ pts, const float* __restrict__ dirs,
    const float* __restrict__ deltas,
    const float* __restrict__ Wr0, const float* __restrict__ br0,
    const float* __restrict__ Wr1, const float* __restrict__ br1,
    const float* __restrict__ beta, const float* __restrict__ variance,
    float* __restrict__ out)
{
    extern __shared__ float sm[];
    float* sW  = sm;             // 8192
    float* sHr = sm + 8192;      // 16384
    float* sX  = sm + 24576;     // 64*56
    int tid = threadIdx.x;
    int pb = blockIdx.x * 64;

    for (int t = tid; t < 192; t += 256) {
        int p = t / 3, a = t - p * 3;
        sX[p * 56 + a]      = pts[(pb + p) * 3 + a];
        sX[p * 56 + 3 + a]  = out[(size_t)NP * 5 + (pb + p) * 3 + a];   // gradients
        sX[p * 56 + 53 + a] = dirs[(pb + p) * 3 + a];
    }
    for (int t = tid; t < 2048; t += 256) { int p = t >> 5, c = t & 31; sX[p * 56 + 6 + c] = g_feats[pb * 32 + t]; }
    for (int t = tid; t < 960; t += 256) { int p = t / 15, j = t - p * 15; sX[p * 56 + 38 + j] = g_geo[pb * 15 + t]; }
    __syncthreads();

    gemm64x256(sX, 56, Wr0, 56, br0, sHr, sW, true, nullptr, nullptr);

    for (int t = tid; t < 768; t += 256) sW[t] = Wr1[t];
    __syncthreads();
    for (int o = tid; o < 192; o += 256) {
        int p = o / 3, c = o - p * 3;
        u64 a2 = pk2(br1[c], 0.f);
        const float* hr = sHr + p * 256;
        for (int k = 0; k < 256; k += 2)
            a2 = ffma2(*(const u64*)(hr + k), pk2(sW[k * 3 + c], sW[k * 3 + 3 + c]), a2);
        float lo, hi; upk2(a2, lo, hi);
        out[(size_t)(pb + p) * 3 + c] = 1.f / (1.f + expf(-(lo + hi)));
    }

    if (tid < 64) {
        int pt = pb + tid;
        float sdf = out[(size_t)NP * 4 + pt];
        float d   = deltas[pt];
        float gx = out[(size_t)NP * 5 + pt * 3],     gy = out[(size_t)NP * 5 + pt * 3 + 1],
              gz = out[(size_t)NP * 5 + pt * 3 + 2];
        float dx = dirs[pt * 3], dy = dirs[pt * 3 + 1], dz = dirs[pt * 3 + 2];
        float be = fabsf(beta[0]) + 1e-4f;
        float sg = (sdf > 0.f) ? 1.f : ((sdf < 0.f) ? -1.f : 0.f);
        float density = (0.5f + 0.5f * sg * expm1f(-fabsf(sdf) / be)) / be;
        float iv = expf(variance[0] * 10.f);
        iv = fminf(fmaxf(iv, 1e-6f), 1e6f);
        float tc = dx * gx + dy * gy + dz * gz;
        float ic = -fmaxf(-tc, 0.f);                 // COS_ANNEAL = 1
        float en = sdf + ic * d * 0.5f;
        float ep = sdf - ic * d * 0.5f;
        float pc = 1.f / (1.f + expf(-ep * iv));
        float nc = 1.f / (1.f + expf(-en * iv));
        float al = (pc - nc + 1e-5f) / (pc + 1e-5f);
        al = fminf(fmaxf(al, 0.f), 1.f);
        out[(size_t)NP * 3 + pt]  = density;
        out[(size_t)NP * 11 + pt] = al;
    }
}

// ---------------- launch ----------------
extern "C" void kernel_launch(void* const* d_in, const int* in_sizes, int n_in,
                              void* d_out, int out_size) {
    const float* points     = (const float*)d_in[0];
    const float* directions = (const float*)d_in[1];
    const float* deltas     = (const float*)d_in[2];
    const float* vol0       = (const float*)d_in[3];
    const float* vol1       = (const float*)d_in[4];
    const float* W0  = (const float*)d_in[5];
    const float* b0  = (const float*)d_in[6];
    const float* W1  = (const float*)d_in[7];
    const float* b1  = (const float*)d_in[8];
    const float* W2  = (const float*)d_in[9];
    const float* b2  = (const float*)d_in[10];
    const float* Wr0 = (const float*)d_in[11];
    const float* br0 = (const float*)d_in[12];
    const float* Wr1 = (const float*)d_in[13];
    const float* br1 = (const float*)d_in[14];
    const float* beta     = (const float*)d_in[15];
    const float* variance = (const float*)d_in[16];
    float* out = (float*)d_out;

    cudaFuncSetAttribute(k_forward,  cudaFuncAttributeMaxDynamicSharedMemorySize, 43264 * 4);
    cudaFuncSetAttribute(k_backward, cudaFuncAttributeMaxDynamicSharedMemorySize, 50368 * 4);
    cudaFuncSetAttribute(k_rgb,      cudaFuncAttributeMaxDynamicSharedMemorySize, 28160 * 4);

    k_transpose<<<128, 256>>>(W0, W1);
    k_sample<<<NP / 64, 64, 8320 * 4>>>(points, vol0, vol1);
    k_forward<<<NP / 64, 256, 43264 * 4>>>(points, W0, b0, W1, b1, W2, b2, out);
    k_backward<<<NP / 64, 256, 50368 * 4>>>(W2, out);
    k_rgb<<<NP / 64, 256, 28160 * 4>>>(points, directions, deltas,
                                       Wr0, br0, Wr1, br1, beta, variance, out);
}

// round 6
// speedup vs baseline: 1.6873x; 1.6873x over previous
#include <cuda_runtime.h>

#define NP 262144          // 2048*128 points
#define GD3 884736         // 96^3

typedef unsigned long long u64;

__device__ __forceinline__ u64 pk2(float lo, float hi) {
    u64 r; asm("mov.b64 %0, {%1,%2};" : "=l"(r) : "f"(lo), "f"(hi)); return r;
}
__device__ __forceinline__ void upk2(u64 v, float& lo, float& hi) {
    asm("mov.b64 {%0,%1}, %2;" : "=f"(lo), "=f"(hi) : "l"(v));
}
__device__ __forceinline__ u64 ffma2(u64 a, u64 b, u64 c) {
    u64 d; asm("fma.rn.f32x2 %0, %1, %2, %3;" : "=l"(d) : "l"(a), "l"(b), "l"(c)); return d;
}

// ---------------- scratch (static device globals; allocation-free) ----------------
__device__ float g_feats[NP * 32];
__device__ float g_dfp[NP * 96];            // [P][3][32] d feat / d p
__device__ float g_H1[(size_t)NP * 256];
__device__ float g_H2[(size_t)NP * 256];
__device__ float g_geo[NP * 15];
__device__ float g_W1T[256 * 256];          // W1T[j][i] = W1[i][j]
__device__ float g_W0T[256 * 35];           // W0T[j][i] = W0[i][j]

// ---------------- weight transpose ----------------
__global__ void k_transpose(const float* __restrict__ W0, const float* __restrict__ W1) {
    int total = 256 * 256 + 256 * 35;
    for (int g = blockIdx.x * blockDim.x + threadIdx.x; g < total; g += gridDim.x * blockDim.x) {
        if (g < 65536) {
            int j = g >> 8, i = g & 255;
            g_W1T[j * 256 + i] = W1[i * 256 + j];
        } else {
            int t = g - 65536;
            int j = t / 35, i = t - j * 35;
            g_W0T[t] = W0[i * 256 + j];
        }
    }
}

// ---------------- trilinear sampling: feats + d feat/d p ----------------
__global__ void k_sample(const float* __restrict__ pts,
                         const float* __restrict__ vol0,
                         const float* __restrict__ vol1) {
    extern __shared__ float sm[];
    float* sFeat = sm;            // 64*33 (padded)
    float* sDfp  = sm + 2112;     // 64*97 (padded)
    int tid = threadIdx.x;
    int p = blockIdx.x * 64 + tid;

    float px = pts[p * 3 + 0], py = pts[p * 3 + 1], pz = pts[p * 3 + 2];
    float x = px * 95.f, y = py * 95.f, z = pz * 95.f;
    int x0 = (int)floorf(x); x0 = min(max(x0, 0), 94);
    int y0 = (int)floorf(y); y0 = min(max(y0, 0), 94);
    int z0 = (int)floorf(z); z0 = min(max(z0, 0), 94);
    float xd = x - (float)x0, yd = y - (float)y0, zd = z - (float)z0;
    float wx0 = 1.f - xd, wx1 = xd;
    float wy0 = 1.f - yd, wy1 = yd;
    float wz0 = 1.f - zd, wz1 = zd;

    int base = (z0 * 96 + y0) * 96 + x0;
    const float* vols[2] = { vol0, vol1 };

    #pragma unroll
    for (int v = 0; v < 2; v++) {
        const float* vb = vols[v] + base;
        #pragma unroll 4
        for (int c = 0; c < 16; c++) {
            const float* q = vb + c * GD3;
            float v000 = __ldg(q);        float v001 = __ldg(q + 1);
            float v010 = __ldg(q + 96);   float v011 = __ldg(q + 97);
            float v100 = __ldg(q + 9216); float v101 = __ldg(q + 9217);
            float v110 = __ldg(q + 9312); float v111 = __ldg(q + 9313);
            float feat = wz0 * (wy0 * (v000 * wx0 + v001 * wx1) + wy1 * (v010 * wx0 + v011 * wx1))
                       + wz1 * (wy0 * (v100 * wx0 + v101 * wx1) + wy1 * (v110 * wx0 + v111 * wx1));
            float dfx = 95.f * (wz0 * (wy0 * (v001 - v000) + wy1 * (v011 - v010))
                              + wz1 * (wy0 * (v101 - v100) + wy1 * (v111 - v110)));
            float dfy = 95.f * (wz0 * (wx0 * (v010 - v000) + wx1 * (v011 - v001))
                              + wz1 * (wx0 * (v110 - v100) + wx1 * (v111 - v101)));
            float dfz = 95.f * (wy0 * (wx0 * (v100 - v000) + wx1 * (v101 - v001))
                              + wy1 * (wx0 * (v110 - v010) + wx1 * (v111 - v011)));
            // feature permutation: [f0 c0..7 | f1 c0..7 | f0 c8..15 | f1 c8..15]
            int fi = (c >> 3) * 16 + v * 8 + (c & 7);
            sFeat[tid * 33 + fi] = feat;
            sDfp[tid * 97 + fi]      = dfx;
            sDfp[tid * 97 + 32 + fi] = dfy;
            sDfp[tid * 97 + 64 + fi] = dfz;
        }
    }
    __syncthreads();
    int fb = blockIdx.x * 64 * 32;
    for (int t = tid; t < 2048; t += 64)
        g_feats[fb + t] = sFeat[(t >> 5) * 33 + (t & 31)];
    int db = blockIdx.x * 64 * 96;
    for (int t = tid; t < 6144; t += 64) {
        int pp = t / 96, q = t - pp * 96;
        g_dfp[db + t] = sDfp[pp * 97 + q];
    }
}

// ---------------- 64-point x 256-out tile GEMM (f32x2, 8x8 microtile) ----------------
// sOut may alias sA: a pre-epilogue __syncthreads() guarantees all warps have
// finished their k-loop reads of sA before any epilogue write lands.
__device__ __forceinline__ void gemm64x256(
    const float* sA, int lda, const float* __restrict__ gW, int KD,
    const float* __restrict__ gBias, float* sOut, float* sW,
    bool do_relu, float* gOut, const float* gMask)
{
    int tid = threadIdx.x;
    int p0 = (tid >> 5) * 8;     // warp -> 8 points
    int j0 = (tid & 31) * 8;     // lane -> 8 output cols
    u64 acc[8][4];
    u64 binit[4];
    #pragma unroll
    for (int jp = 0; jp < 4; jp++)
        binit[jp] = gBias ? pk2(gBias[j0 + 2 * jp], gBias[j0 + 2 * jp + 1]) : 0ull;
    #pragma unroll
    for (int i = 0; i < 8; i++)
        #pragma unroll
        for (int jp = 0; jp < 4; jp++) acc[i][jp] = binit[jp];

    for (int k0 = 0; k0 < KD; k0 += 32) {
        int kc = KD - k0; if (kc > 32) kc = 32;
        __syncthreads();
        for (int t = tid; t < kc * 64; t += 256) {
            int r = t >> 6, c = t & 63;
            ((float4*)sW)[r * 64 + c] = ((const float4*)(gW + (size_t)(k0 + r) * 256))[c];
        }
        __syncthreads();
        if (kc == 32) {
            #pragma unroll
            for (int k = 0; k < 32; k++) {
                u64 a2[8];
                #pragma unroll
                for (int i = 0; i < 8; i++) {
                    float av = sA[(p0 + i) * lda + k0 + k];
                    a2[i] = pk2(av, av);
                }
                float4 wA = *(const float4*)(sW + k * 256 + j0);
                float4 wB = *(const float4*)(sW + k * 256 + j0 + 4);
                u64 w2[4] = { pk2(wA.x, wA.y), pk2(wA.z, wA.w),
                              pk2(wB.x, wB.y), pk2(wB.z, wB.w) };
                #pragma unroll
                for (int i = 0; i < 8; i++)
                    #pragma unroll
                    for (int jp = 0; jp < 4; jp++)
                        acc[i][jp] = ffma2(a2[i], w2[jp], acc[i][jp]);
            }
        } else {
            for (int k = 0; k < kc; k++) {
                u64 a2[8];
                #pragma unroll
                for (int i = 0; i < 8; i++) {
                    float av = sA[(p0 + i) * lda + k0 + k];
                    a2[i] = pk2(av, av);
                }
                float4 wA = *(const float4*)(sW + k * 256 + j0);
                float4 wB = *(const float4*)(sW + k * 256 + j0 + 4);
                u64 w2[4] = { pk2(wA.x, wA.y), pk2(wA.z, wA.w),
                              pk2(wB.x, wB.y), pk2(wB.z, wB.w) };
                #pragma unroll
                for (int i = 0; i < 8; i++)
                    #pragma unroll
                    for (int jp = 0; jp < 4; jp++)
                        acc[i][jp] = ffma2(a2[i], w2[jp], acc[i][jp]);
            }
        }
    }
    __syncthreads();   // allow sOut == sA
    #pragma unroll
    for (int i = 0; i < 8; i++) {
        float vv[8];
        #pragma unroll
        for (int jp = 0; jp < 4; jp++) upk2(acc[i][jp], vv[2 * jp], vv[2 * jp + 1]);
        if (do_relu) {
            #pragma unroll
            for (int j = 0; j < 8; j++) vv[j] = fmaxf(vv[j], 0.f);
        }
        if (gMask) {
            float4 m0 = *(const float4*)(gMask + (size_t)(p0 + i) * 256 + j0);
            float4 m1 = *(const float4*)(gMask + (size_t)(p0 + i) * 256 + j0 + 4);
            float mm[8] = { m0.x, m0.y, m0.z, m0.w, m1.x, m1.y, m1.z, m1.w };
            #pragma unroll
            for (int j = 0; j < 8; j++) vv[j] = (mm[j] > 0.f) ? vv[j] : 0.f;
        }
        float4 o0 = make_float4(vv[0], vv[1], vv[2], vv[3]);
        float4 o1 = make_float4(vv[4], vv[5], vv[6], vv[7]);
        *(float4*)(sOut + (p0 + i) * 256 + j0)     = o0;
        *(float4*)(sOut + (p0 + i) * 256 + j0 + 4) = o1;
        if (gOut) {
            *(float4*)(gOut + (size_t)(p0 + i) * 256 + j0)     = o0;
            *(float4*)(gOut + (size_t)(p0 + i) * 256 + j0 + 4) = o1;
        }
    }
    __syncthreads();
}

// ---------------- forward MLP: L0 + L1 (H2 overwrites sH1) + L2 head ----------------
__global__ __launch_bounds__(256, 2) void k_forward(
    const float* __restrict__ pts,
    const float* __restrict__ W0, const float* __restrict__ b0,
    const float* __restrict__ W1, const float* __restrict__ b1,
    const float* __restrict__ W2, const float* __restrict__ b2,
    float* __restrict__ out)
{
    extern __shared__ float sm[];
    float* sW  = sm;             // 8192
    float* sH1 = sm + 8192;      // 16384  (holds H1, then H2)
    float* sX  = sm + 24576;     // 64*36 = 2304
    int tid = threadIdx.x;
    int pb = blockIdx.x * 64;

    for (int t = tid; t < 192; t += 256) { int p = t / 3, a = t - p * 3; sX[p * 36 + a] = pts[(pb + p) * 3 + a]; }
    for (int t = tid; t < 2048; t += 256) { int p = t >> 5, c = t & 31; sX[p * 36 + 3 + c] = g_feats[pb * 32 + t]; }
    __syncthreads();

    gemm64x256(sX, 36, W0, 35, b0, sH1, sW, true, g_H1 + (size_t)pb * 256, nullptr);
    // H2 overwrites sH1 (aliased; gemm syncs before epilogue)
    gemm64x256(sH1, 256, W1, 256, b1, sH1, sW, true, g_H2 + (size_t)pb * 256, nullptr);

    // layer 3: 256 -> 16  (W2 staged in sW), H2 read from sH1
    for (int t = tid; t < 1024; t += 256) ((float4*)sW)[t] = ((const float4*)W2)[t];
    __syncthreads();
    int jc = tid & 15, pr = tid >> 4;
    u64 acc2[4];
    float bb = b2[jc];
    #pragma unroll
    for (int i = 0; i < 4; i++) acc2[i] = pk2(bb, 0.f);
    for (int k = 0; k < 256; k += 2) {
        u64 w2 = pk2(sW[k * 16 + jc], sW[k * 16 + 16 + jc]);
        #pragma unroll
        for (int i = 0; i < 4; i++)
            acc2[i] = ffma2(*(const u64*)(sH1 + (pr * 4 + i) * 256 + k), w2, acc2[i]);
    }
    #pragma unroll
    for (int i = 0; i < 4; i++) {
        float lo, hi; upk2(acc2[i], lo, hi);
        float a = lo + hi;
        int pt = pb + pr * 4 + i;
        if (jc == 0) out[(size_t)NP * 4 + pt] = a;
        else         g_geo[pt * 15 + jc - 1] = a;
    }
}

// ---------------- backward: gradients of sdf wrt points ----------------
__global__ __launch_bounds__(256, 2) void k_backward(
    const float* __restrict__ W2, float* __restrict__ out)
{
    extern __shared__ float sm[];
    float* sW   = sm;            // 8960 (W1T k-chunk / W0T)
    float* sG   = sm + 8960;     // 16384  (G2, then G1 aliased)
    float* sGx  = sm + 25344;    // 2240
    float* sB   = sm + 27584;    // 256
    int tid = threadIdx.x;
    int pb = blockIdx.x * 64;

    sB[tid] = W2[tid * 16];      // W2 column 0
    __syncthreads();

    const float4* h2 = (const float4*)(g_H2 + (size_t)pb * 256);
    for (int t = tid; t < 4096; t += 256) {
        float4 h = h2[t];
        int j = (t & 63) * 4;
        float4 g;
        g.x = h.x > 0.f ? sB[j]     : 0.f;
        g.y = h.y > 0.f ? sB[j + 1] : 0.f;
        g.z = h.z > 0.f ? sB[j + 2] : 0.f;
        g.w = h.w > 0.f ? sB[j + 3] : 0.f;
        ((float4*)sG)[t] = g;
    }
    // G1 = (G2 @ W1^T) * (H1 > 0), written in place over G2
    gemm64x256(sG, 256, g_W1T, 256, nullptr, sG, sW, false, nullptr, g_H1 + (size_t)pb * 256);

    // Gx = G1 @ W0^T  (N = 35)
    for (int t = tid; t < 2240; t += 256) ((float4*)sW)[t] = ((const float4*)g_W0T)[t];
    __syncthreads();
    for (int o = tid; o < 2240; o += 256) {
        int p = o / 35, i = o - p * 35;
        u64 a2 = 0ull;
        const float* gr = sG + p * 256;
        for (int k = 0; k < 256; k += 2)
            a2 = ffma2(*(const u64*)(gr + k), pk2(sW[k * 35 + i], sW[k * 35 + 35 + i]), a2);
        float lo, hi; upk2(a2, lo, hi);
        sGx[o] = lo + hi;
    }
    __syncthreads();
    if (tid < 64) {
        int p = tid, pt = pb + p;
        const float* dfp = g_dfp + (size_t)pt * 96;
        float gx = sGx[p * 35], gy = sGx[p * 35 + 1], gz = sGx[p * 35 + 2];
        #pragma unroll
        for (int c = 0; c < 32; c++) {
            float q = sGx[p * 35 + 3 + c];
            gx = fmaf(q, __ldg(dfp + c),      gx);
            gy = fmaf(q, __ldg(dfp + 32 + c), gy);
            gz = fmaf(q, __ldg(dfp + 64 + c), gz);
        }
        out[(size_t)NP * 5 + pt * 3 + 0] = gx;
        out[(size_t)NP * 5 + pt * 3 + 1] = gy;
        out[(size_t)NP * 5 + pt * 3 + 2] = gz;
        float n = sqrtf(gx * gx + gy * gy + gz * gz);
        float inv = 1.f / fmaxf(n, 1e-12f);
        out[(size_t)NP * 8 + pt * 3 + 0] = gx * inv;
        out[(size_t)NP * 8 + pt * 3 + 1] = gy * inv;
        out[(size_t)NP * 8 + pt * 3 + 2] = gz * inv;
    }
}

// ---------------- RGB head + elementwise outputs ----------------
__global__ __launch_bounds__(256, 2) void k_rgb(
    const float* __restrict__ pts, const float* __restrict__ dirs,
    const float* __restrict__ deltas,
    const float* __restrict__ Wr0, const float* __restrict__ br0,
    const float* __restrict__ Wr1, const float* __restrict__ br1,
    const float* __restrict__ beta, const float* __restrict__ variance,
    float* __restrict__ out)
{
    extern __shared__ float sm[];
    float* sW  = sm;             // 8192
    float* sHr = sm + 8192;      // 16384
    float* sX  = sm + 24576;     // 64*56 = 3584
    int tid = threadIdx.x;
    int pb = blockIdx.x * 64;

    for (int t = tid; t < 192; t += 256) {
        int p = t / 3, a = t - p * 3;
        sX[p * 56 + a]      = pts[(pb + p) * 3 + a];
        sX[p * 56 + 3 + a]  = out[(size_t)NP * 5 + (pb + p) * 3 + a];   // gradients
        sX[p * 56 + 53 + a] = dirs[(pb + p) * 3 + a];
    }
    for (int t = tid; t < 2048; t += 256) { int p = t >> 5, c = t & 31; sX[p * 56 + 6 + c] = g_feats[pb * 32 + t]; }
    for (int t = tid; t < 960; t += 256) { int p = t / 15, j = t - p * 15; sX[p * 56 + 38 + j] = g_geo[pb * 15 + t]; }
    __syncthreads();

    gemm64x256(sX, 56, Wr0, 56, br0, sHr, sW, true, nullptr, nullptr);

    for (int t = tid; t < 768; t += 256) sW[t] = Wr1[t];
    __syncthreads();
    for (int o = tid; o < 192; o += 256) {
        int p = o / 3, c = o - p * 3;
        u64 a2 = pk2(br1[c], 0.f);
        const float* hr = sHr + p * 256;
        for (int k = 0; k < 256; k += 2)
            a2 = ffma2(*(const u64*)(hr + k), pk2(sW[k * 3 + c], sW[k * 3 + 3 + c]), a2);
        float lo, hi; upk2(a2, lo, hi);
        out[(size_t)(pb + p) * 3 + c] = 1.f / (1.f + expf(-(lo + hi)));
    }

    if (tid < 64) {
        int pt = pb + tid;
        float sdf = out[(size_t)NP * 4 + pt];
        float d   = deltas[pt];
        float gx = out[(size_t)NP * 5 + pt * 3],     gy = out[(size_t)NP * 5 + pt * 3 + 1],
              gz = out[(size_t)NP * 5 + pt * 3 + 2];
        float dx = dirs[pt * 3], dy = dirs[pt * 3 + 1], dz = dirs[pt * 3 + 2];
        float be = fabsf(beta[0]) + 1e-4f;
        float sg = (sdf > 0.f) ? 1.f : ((sdf < 0.f) ? -1.f : 0.f);
        float density = (0.5f + 0.5f * sg * expm1f(-fabsf(sdf) / be)) / be;
        float iv = expf(variance[0] * 10.f);
        iv = fminf(fmaxf(iv, 1e-6f), 1e6f);
        float tc = dx * gx + dy * gy + dz * gz;
        float ic = -fmaxf(-tc, 0.f);                 // COS_ANNEAL = 1
        float en = sdf + ic * d * 0.5f;
        float ep = sdf - ic * d * 0.5f;
        float pc = 1.f / (1.f + expf(-ep * iv));
        float nc = 1.f / (1.f + expf(-en * iv));
        float al = (pc - nc + 1e-5f) / (pc + 1e-5f);
        al = fminf(fmaxf(al, 0.f), 1.f);
        out[(size_t)NP * 3 + pt]  = density;
        out[(size_t)NP * 11 + pt] = al;
    }
}

// ---------------- launch ----------------
extern "C" void kernel_launch(void* const* d_in, const int* in_sizes, int n_in,
                              void* d_out, int out_size) {
    const float* points     = (const float*)d_in[0];
    const float* directions = (const float*)d_in[1];
    const float* deltas     = (const float*)d_in[2];
    const float* vol0       = (const float*)d_in[3];
    const float* vol1       = (const float*)d_in[4];
    const float* W0  = (const float*)d_in[5];
    const float* b0  = (const float*)d_in[6];
    const float* W1  = (const float*)d_in[7];
    const float* b1  = (const float*)d_in[8];
    const float* W2  = (const float*)d_in[9];
    const float* b2  = (const float*)d_in[10];
    const float* Wr0 = (const float*)d_in[11];
    const float* br0 = (const float*)d_in[12];
    const float* Wr1 = (const float*)d_in[13];
    const float* br1 = (const float*)d_in[14];
    const float* beta     = (const float*)d_in[15];
    const float* variance = (const float*)d_in[16];
    float* out = (float*)d_out;

    cudaFuncSetAttribute(k_forward,  cudaFuncAttributeMaxDynamicSharedMemorySize, 26880 * 4);
    cudaFuncSetAttribute(k_backward, cudaFuncAttributeMaxDynamicSharedMemorySize, 27840 * 4);
    cudaFuncSetAttribute(k_rgb,      cudaFuncAttributeMaxDynamicSharedMemorySize, 28160 * 4);

    k_transpose<<<128, 256>>>(W0, W1);
    k_sample<<<NP / 64, 64, 8320 * 4>>>(points, vol0, vol1);
    k_forward<<<NP / 64, 256, 26880 * 4>>>(points, W0, b0, W1, b1, W2, b2, out);
    k_backward<<<NP / 64, 256, 27840 * 4>>>(W2, out);
    k_rgb<<<NP / 64, 256, 28160 * 4>>>(points, directions, deltas,
                                       Wr0, br0, Wr1, br1, beta, variance, out);
}

// round 8
// speedup vs baseline: 1.7697x; 1.0489x over previous
#include <cuda_runtime.h>

#define NP 262144          // 2048*128 points
#define GD3 884736         // 96^3

typedef unsigned long long u64;

__device__ __forceinline__ u64 pk2(float lo, float hi) {
    u64 r; asm("mov.b64 %0, {%1,%2};" : "=l"(r) : "f"(lo), "f"(hi)); return r;
}
__device__ __forceinline__ void upk2(u64 v, float& lo, float& hi) {
    asm("mov.b64 {%0,%1}, %2;" : "=f"(lo), "=f"(hi) : "l"(v));
}
__device__ __forceinline__ u64 ffma2(u64 a, u64 b, u64 c) {
    u64 d; asm("fma.rn.f32x2 %0, %1, %2, %3;" : "=l"(d) : "l"(a), "l"(b), "l"(c)); return d;
}

// ---------------- scratch (static device globals; allocation-free) ----------------
__device__ float g_feats[NP * 32];
__device__ float g_dfp[NP * 96];            // [P][3][32] d feat / d p
__device__ float g_H1[(size_t)NP * 256];
__device__ float g_H2[(size_t)NP * 256];
__device__ float g_geo[NP * 15];
__device__ float g_W1T[256 * 256];          // W1T[j][i] = W1[i][j]
__device__ float g_W0T[256 * 35];           // W0T[j][i] = W0[i][j]

// ---------------- weight transpose ----------------
__global__ void k_transpose(const float* __restrict__ W0, const float* __restrict__ W1) {
    int total = 256 * 256 + 256 * 35;
    for (int g = blockIdx.x * blockDim.x + threadIdx.x; g < total; g += gridDim.x * blockDim.x) {
        if (g < 65536) {
            int j = g >> 8, i = g & 255;
            g_W1T[j * 256 + i] = W1[i * 256 + j];
        } else {
            int t = g - 65536;
            int j = t / 35, i = t - j * 35;
            g_W0T[t] = W0[i * 256 + j];
        }
    }
}

// ---------------- trilinear sampling: feats + d feat/d p ----------------
__global__ void k_sample(const float* __restrict__ pts,
                         const float* __restrict__ vol0,
                         const float* __restrict__ vol1) {
    extern __shared__ float sm[];
    float* sFeat = sm;            // 64*33 (padded)
    float* sDfp  = sm + 2112;     // 64*97 (padded)
    int tid = threadIdx.x;
    int p = blockIdx.x * 64 + tid;

    float px = pts[p * 3 + 0], py = pts[p * 3 + 1], pz = pts[p * 3 + 2];
    float x = px * 95.f, y = py * 95.f, z = pz * 95.f;
    int x0 = (int)floorf(x); x0 = min(max(x0, 0), 94);
    int y0 = (int)floorf(y); y0 = min(max(y0, 0), 94);
    int z0 = (int)floorf(z); z0 = min(max(z0, 0), 94);
    float xd = x - (float)x0, yd = y - (float)y0, zd = z - (float)z0;
    float wx0 = 1.f - xd, wx1 = xd;
    float wy0 = 1.f - yd, wy1 = yd;
    float wz0 = 1.f - zd, wz1 = zd;

    int base = (z0 * 96 + y0) * 96 + x0;
    const float* vols[2] = { vol0, vol1 };

    #pragma unroll
    for (int v = 0; v < 2; v++) {
        const float* vb = vols[v] + base;
        #pragma unroll 4
        for (int c = 0; c < 16; c++) {
            const float* q = vb + c * GD3;
            float v000 = __ldg(q);        float v001 = __ldg(q + 1);
            float v010 = __ldg(q + 96);   float v011 = __ldg(q + 97);
            float v100 = __ldg(q + 9216); float v101 = __ldg(q + 9217);
            float v110 = __ldg(q + 9312); float v111 = __ldg(q + 9313);
            float feat = wz0 * (wy0 * (v000 * wx0 + v001 * wx1) + wy1 * (v010 * wx0 + v011 * wx1))
                       + wz1 * (wy0 * (v100 * wx0 + v101 * wx1) + wy1 * (v110 * wx0 + v111 * wx1));
            float dfx = 95.f * (wz0 * (wy0 * (v001 - v000) + wy1 * (v011 - v010))
                              + wz1 * (wy0 * (v101 - v100) + wy1 * (v111 - v110)));
            float dfy = 95.f * (wz0 * (wx0 * (v010 - v000) + wx1 * (v011 - v001))
                              + wz1 * (wx0 * (v110 - v100) + wx1 * (v111 - v101)));
            float dfz = 95.f * (wy0 * (wx0 * (v100 - v000) + wx1 * (v101 - v001))
                              + wy1 * (wx0 * (v110 - v010) + wx1 * (v111 - v011)));
            // feature permutation: [f0 c0..7 | f1 c0..7 | f0 c8..15 | f1 c8..15]
            int fi = (c >> 3) * 16 + v * 8 + (c & 7);
            sFeat[tid * 33 + fi] = feat;
            sDfp[tid * 97 + fi]      = dfx;
            sDfp[tid * 97 + 32 + fi] = dfy;
            sDfp[tid * 97 + 64 + fi] = dfz;
        }
    }
    __syncthreads();
    int fb = blockIdx.x * 64 * 32;
    for (int t = tid; t < 2048; t += 64)
        g_feats[fb + t] = sFeat[(t >> 5) * 33 + (t & 31)];
    int db = blockIdx.x * 64 * 96;
    for (int t = tid; t < 6144; t += 64) {
        int pp = t / 96, q = t - pp * 96;
        g_dfp[db + t] = sDfp[pp * 97 + q];
    }
}

// ---------------- 64-point x 256-out tile GEMM (f32x2, 8x8 microtile) ----------------
// Lane owns cols [4*lane .. 4*lane+3] and [128+4*lane .. +3] -> LDS.128 weight
// loads are contiguous across the warp (16B lane stride, conflict-free), and
// each float4 yields two contiguous f32x2 operand pairs.
// A-operands are loaded as LDS.64 k-pairs (contiguous in the point-major row).
// sOut may alias sA: a pre-epilogue __syncthreads() protects the k-loop reads.
__device__ __forceinline__ void gemm64x256(
    const float* sA, int lda, const float* __restrict__ gW, int KD,
    const float* __restrict__ gBias, float* sOut, float* sW,
    bool do_relu, float* gOut, const float* gMask)
{
    int tid = threadIdx.x;
    int p0 = (tid >> 5) * 8;     // warp -> 8 points
    int lane = tid & 31;
    int j0a = 4 * lane;          // cols j0a..j0a+3
    int j0b = 128 + 4 * lane;    // cols j0b..j0b+3
    u64 acc[8][4];
    u64 binit[4];
    if (gBias) {
        binit[0] = *(const u64*)(gBias + j0a);
        binit[1] = *(const u64*)(gBias + j0a + 2);
        binit[2] = *(const u64*)(gBias + j0b);
        binit[3] = *(const u64*)(gBias + j0b + 2);
    } else {
        binit[0] = binit[1] = binit[2] = binit[3] = 0ull;
    }
    #pragma unroll
    for (int i = 0; i < 8; i++)
        #pragma unroll
        for (int jp = 0; jp < 4; jp++) acc[i][jp] = binit[jp];

    for (int k0 = 0; k0 < KD; k0 += 32) {
        int kc = KD - k0; if (kc > 32) kc = 32;
        __syncthreads();
        for (int t = tid; t < kc * 64; t += 256) {
            int r = t >> 6, c = t & 63;
            ((float4*)sW)[r * 64 + c] = ((const float4*)(gW + (size_t)(k0 + r) * 256))[c];
        }
        __syncthreads();
        if (kc == 32) {
            #pragma unroll
            for (int kk = 0; kk < 32; kk += 2) {
                u64 ap[8];
                #pragma unroll
                for (int i = 0; i < 8; i++)
                    ap[i] = *(const u64*)(sA + (p0 + i) * lda + k0 + kk);
                float4 wA0 = *(const float4*)(sW + kk * 256 + j0a);
                float4 wB0 = *(const float4*)(sW + kk * 256 + j0b);
                float4 wA1 = *(const float4*)(sW + (kk + 1) * 256 + j0a);
                float4 wB1 = *(const float4*)(sW + (kk + 1) * 256 + j0b);
                u64 w0[4] = { pk2(wA0.x, wA0.y), pk2(wA0.z, wA0.w),
                              pk2(wB0.x, wB0.y), pk2(wB0.z, wB0.w) };
                u64 w1[4] = { pk2(wA1.x, wA1.y), pk2(wA1.z, wA1.w),
                              pk2(wB1.x, wB1.y), pk2(wB1.z, wB1.w) };
                #pragma unroll
                for (int i = 0; i < 8; i++) {
                    float alo, ahi; upk2(ap[i], alo, ahi);
                    u64 a0 = pk2(alo, alo), a1 = pk2(ahi, ahi);
                    #pragma unroll
                    for (int jp = 0; jp < 4; jp++)
                        acc[i][jp] = ffma2(a0, w0[jp], acc[i][jp]);
                    #pragma unroll
                    for (int jp = 0; jp < 4; jp++)
                        acc[i][jp] = ffma2(a1, w1[jp], acc[i][jp]);
                }
            }
        } else {
            int kk = 0;
            for (; kk + 1 < kc; kk += 2) {
                u64 ap[8];
                #pragma unroll
                for (int i = 0; i < 8; i++)
                    ap[i] = *(const u64*)(sA + (p0 + i) * lda + k0 + kk);
                float4 wA0 = *(const float4*)(sW + kk * 256 + j0a);
                float4 wB0 = *(const float4*)(sW + kk * 256 + j0b);
                float4 wA1 = *(const float4*)(sW + (kk + 1) * 256 + j0a);
                float4 wB1 = *(const float4*)(sW + (kk + 1) * 256 + j0b);
                u64 w0[4] = { pk2(wA0.x, wA0.y), pk2(wA0.z, wA0.w),
                              pk2(wB0.x, wB0.y), pk2(wB0.z, wB0.w) };
                u64 w1[4] = { pk2(wA1.x, wA1.y), pk2(wA1.z, wA1.w),
                              pk2(wB1.x, wB1.y), pk2(wB1.z, wB1.w) };
                #pragma unroll
                for (int i = 0; i < 8; i++) {
                    float alo, ahi; upk2(ap[i], alo, ahi);
                    u64 a0 = pk2(alo, alo), a1 = pk2(ahi, ahi);
                    #pragma unroll
                    for (int jp = 0; jp < 4; jp++)
                        acc[i][jp] = ffma2(a0, w0[jp], acc[i][jp]);
                    #pragma unroll
                    for (int jp = 0; jp < 4; jp++)
                        acc[i][jp] = ffma2(a1, w1[jp], acc[i][jp]);
                }
            }
            if (kc & 1) {
                int k = kc - 1;
                float4 wA = *(const float4*)(sW + k * 256 + j0a);
                float4 wB = *(const float4*)(sW + k * 256 + j0b);
                u64 w2[4] = { pk2(wA.x, wA.y), pk2(wA.z, wA.w),
                              pk2(wB.x, wB.y), pk2(wB.z, wB.w) };
                #pragma unroll
                for (int i = 0; i < 8; i++) {
                    float av = sA[(p0 + i) * lda + k0 + k];
                    u64 a2 = pk2(av, av);
                    #pragma unroll
                    for (int jp = 0; jp < 4; jp++)
                        acc[i][jp] = ffma2(a2, w2[jp], acc[i][jp]);
                }
            }
        }
    }
    __syncthreads();   // allow sOut == sA
    #pragma unroll
    for (int i = 0; i < 8; i++) {
        float vv[8];
        upk2(acc[i][0], vv[0], vv[1]);
        upk2(acc[i][1], vv[2], vv[3]);
        upk2(acc[i][2], vv[4], vv[5]);
        upk2(acc[i][3], vv[6], vv[7]);
        if (do_relu) {
            #pragma unroll
            for (int j = 0; j < 8; j++) vv[j] = fmaxf(vv[j], 0.f);
        }
        if (gMask) {
            float4 m0 = *(const float4*)(gMask + (size_t)(p0 + i) * 256 + j0a);
            float4 m1 = *(const float4*)(gMask + (size_t)(p0 + i) * 256 + j0b);
            float mm[8] = { m0.x, m0.y, m0.z, m0.w, m1.x, m1.y, m1.z, m1.w };
            #pragma unroll
            for (int j = 0; j < 8; j++) vv[j] = (mm[j] > 0.f) ? vv[j] : 0.f;
        }
        float4 o0 = make_float4(vv[0], vv[1], vv[2], vv[3]);
        float4 o1 = make_float4(vv[4], vv[5], vv[6], vv[7]);
        *(float4*)(sOut + (p0 + i) * 256 + j0a) = o0;
        *(float4*)(sOut + (p0 + i) * 256 + j0b) = o1;
        if (gOut) {
            *(float4*)(gOut + (size_t)(p0 + i) * 256 + j0a) = o0;
            *(float4*)(gOut + (size_t)(p0 + i) * 256 + j0b) = o1;
        }
    }
    __syncthreads();
}

// ---------------- forward MLP: L0 + L1 (H2 overwrites sH1) + L2 head ----------------
__global__ __launch_bounds__(256, 2) void k_forward(
    const float* __restrict__ pts,
    const float* __restrict__ W0, const float* __restrict__ b0,
    const float* __restrict__ W1, const float* __restrict__ b1,
    const float* __restrict__ W2, const float* __restrict__ b2,
    float* __restrict__ out)
{
    extern __shared__ float sm[];
    float* sW  = sm;             // 8192
    float* sH1 = sm + 8192;      // 16384  (holds H1, then H2)
    float* sX  = sm + 24576;     // 64*36 = 2304
    int tid = threadIdx.x;
    int pb = blockIdx.x * 64;

    for (int t = tid; t < 192; t += 256) { int p = t / 3, a = t - p * 3; sX[p * 36 + a] = pts[(pb + p) * 3 + a]; }
    for (int t = tid; t < 2048; t += 256) { int p = t >> 5, c = t & 31; sX[p * 36 + 3 + c] = g_feats[pb * 32 + t]; }
    __syncthreads();

    gemm64x256(sX, 36, W0, 35, b0, sH1, sW, true, g_H1 + (size_t)pb * 256, nullptr);
    // H2 overwrites sH1 (aliased; gemm syncs before epilogue)
    gemm64x256(sH1, 256, W1, 256, b1, sH1, sW, true, g_H2 + (size_t)pb * 256, nullptr);

    // layer 3: 256 -> 16  (W2 staged in sW), H2 read from sH1
    for (int t = tid; t < 1024; t += 256) ((float4*)sW)[t] = ((const float4*)W2)[t];
    __syncthreads();
    int jc = tid & 15, pr = tid >> 4;
    u64 acc2[4];
    float bb = b2[jc];
    #pragma unroll
    for (int i = 0; i < 4; i++) acc2[i] = pk2(bb, 0.f);
    for (int k = 0; k < 256; k += 2) {
        u64 w2 = pk2(sW[k * 16 + jc], sW[k * 16 + 16 + jc]);
        #pragma unroll
        for (int i = 0; i < 4; i++)
            acc2[i] = ffma2(*(const u64*)(sH1 + (pr * 4 + i) * 256 + k), w2, acc2[i]);
    }
    #pragma unroll
    for (int i = 0; i < 4; i++) {
        float lo, hi; upk2(acc2[i], lo, hi);
        float a = lo + hi;
        int pt = pb + pr * 4 + i;
        if (jc == 0) out[(size_t)NP * 4 + pt] = a;
        else         g_geo[pt * 15 + jc - 1] = a;
    }
}

// ---------------- backward: gradients of sdf wrt points ----------------
__global__ __launch_bounds__(256, 2) void k_backward(
    const float* __restrict__ W2, float* __restrict__ out)
{
    extern __shared__ float sm[];
    float* sW   = sm;            // 8960 (W1T k-chunk / W0T)
    float* sG   = sm + 8960;     // 16384  (G2, then G1 aliased)
    float* sGx  = sm + 25344;    // 2240
    float* sB   = sm + 27584;    // 256
    int tid = threadIdx.x;
    int pb = blockIdx.x * 64;

    sB[tid] = W2[tid * 16];      // W2 column 0
    __syncthreads();

    const float4* h2 = (const float4*)(g_H2 + (size_t)pb * 256);
    for (int t = tid; t < 4096; t += 256) {
        float4 h = h2[t];
        int j = (t & 63) * 4;
        float4 g;
        g.x = h.x > 0.f ? sB[j]     : 0.f;
        g.y = h.y > 0.f ? sB[j + 1] : 0.f;
        g.z = h.z > 0.f ? sB[j + 2] : 0.f;
        g.w = h.w > 0.f ? sB[j + 3] : 0.f;
        ((float4*)sG)[t] = g;
    }
    // G1 = (G2 @ W1^T) * (H1 > 0), written in place over G2
    gemm64x256(sG, 256, g_W1T, 256, nullptr, sG, sW, false, nullptr, g_H1 + (size_t)pb * 256);

    // Gx = G1 @ W0^T  (N = 35)
    for (int t = tid; t < 2240; t += 256) ((float4*)sW)[t] = ((const float4*)g_W0T)[t];
    __syncthreads();
    for (int o = tid; o < 2240; o += 256) {
        int p = o / 35, i = o - p * 35;
        u64 a2 = 0ull;
        const float* gr = sG + p * 256;
        for (int k = 0; k < 256; k += 2)
            a2 = ffma2(*(const u64*)(gr + k), pk2(sW[k * 35 + i], sW[k * 35 + 35 + i]), a2);
        float lo, hi; upk2(a2, lo, hi);
        sGx[o] = lo + hi;
    }
    __syncthreads();
    if (tid < 64) {
        int p = tid, pt = pb + p;
        const float* dfp = g_dfp + (size_t)pt * 96;
        float gx = sGx[p * 35], gy = sGx[p * 35 + 1], gz = sGx[p * 35 + 2];
        #pragma unroll
        for (int c = 0; c < 32; c++) {
            float q = sGx[p * 35 + 3 + c];
            gx = fmaf(q, __ldg(dfp + c),      gx);
            gy = fmaf(q, __ldg(dfp + 32 + c), gy);
            gz = fmaf(q, __ldg(dfp + 64 + c), gz);
        }
        out[(size_t)NP * 5 + pt * 3 + 0] = gx;
        out[(size_t)NP * 5 + pt * 3 + 1] = gy;
        out[(size_t)NP * 5 + pt * 3 + 2] = gz;
        float n = sqrtf(gx * gx + gy * gy + gz * gz);
        float inv = 1.f / fmaxf(n, 1e-12f);
        out[(size_t)NP * 8 + pt * 3 + 0] = gx * inv;
        out[(size_t)NP * 8 + pt * 3 + 1] = gy * inv;
        out[(size_t)NP * 8 + pt * 3 + 2] = gz * inv;
    }
}

// ---------------- RGB head + elementwise outputs ----------------
__global__ __launch_bounds__(256, 2) void k_rgb(
    const float* __restrict__ pts, const float* __restrict__ dirs,
    const float* __restrict__ deltas,
    const float* __restrict__ Wr0, const float* __restrict__ br0,
    const float* __restrict__ Wr1, const float* __restrict__ br1,
    const float* __restrict__ beta, const float* __restrict__ variance,
    float* __restrict__ out)
{
    extern __shared__ float sm[];
    float* sW  = sm;             // 8192
    float* sHr = sm + 8192;      // 16384
    float* sX  = sm + 24576;     // 64*56 = 3584
    int tid = threadIdx.x;
    int pb = blockIdx.x * 64;

    for (int t = tid; t < 192; t += 256) {
        int p = t / 3, a = t - p * 3;
        sX[p * 56 + a]      = pts[(pb + p) * 3 + a];
        sX[p * 56 + 3 + a]  = out[(size_t)NP * 5 + (pb + p) * 3 + a];   // gradients
        sX[p * 56 + 53 + a] = dirs[(pb + p) * 3 + a];
    }
    for (int t = tid; t < 2048; t += 256) { int p = t >> 5, c = t & 31; sX[p * 56 + 6 + c] = g_feats[pb * 32 + t]; }
    for (int t = tid; t < 960; t += 256) { int p = t / 15, j = t - p * 15; sX[p * 56 + 38 + j] = g_geo[pb * 15 + t]; }
    __syncthreads();

    gemm64x256(sX, 56, Wr0, 56, br0, sHr, sW, true, nullptr, nullptr);

    for (int t = tid; t < 768; t += 256) sW[t] = Wr1[t];
    __syncthreads();
    for (int o = tid; o < 192; o += 256) {
        int p = o / 3, c = o - p * 3;
        u64 a2 = pk2(br1[c], 0.f);
        const float* hr = sHr + p * 256;
        for (int k = 0; k < 256; k += 2)
            a2 = ffma2(*(const u64*)(hr + k), pk2(sW[k * 3 + c], sW[k * 3 + 3 + c]), a2);
        float lo, hi; upk2(a2, lo, hi);
        out[(size_t)(pb + p) * 3 + c] = 1.f / (1.f + expf(-(lo + hi)));
    }

    if (tid < 64) {
        int pt = pb + tid;
        float sdf = out[(size_t)NP * 4 + pt];
        float d   = deltas[pt];
        float gx = out[(size_t)NP * 5 + pt * 3],     gy = out[(size_t)NP * 5 + pt * 3 + 1],
              gz = out[(size_t)NP * 5 + pt * 3 + 2];
        float dx = dirs[pt * 3], dy = dirs[pt * 3 + 1], dz = dirs[pt * 3 + 2];
        float be = fabsf(beta[0]) + 1e-4f;
        float sg = (sdf > 0.f) ? 1.f : ((sdf < 0.f) ? -1.f : 0.f);
        float density = (0.5f + 0.5f * sg * expm1f(-fabsf(sdf) / be)) / be;
        float iv = expf(variance[0] * 10.f);
        iv = fminf(fmaxf(iv, 1e-6f), 1e6f);
        float tc = dx * gx + dy * gy + dz * gz;
        float ic = -fmaxf(-tc, 0.f);                 // COS_ANNEAL = 1
        float en = sdf + ic * d * 0.5f;
        float ep = sdf - ic * d * 0.5f;
        float pc = 1.f / (1.f + expf(-ep * iv));
        float nc = 1.f / (1.f + expf(-en * iv));
        float al = (pc - nc + 1e-5f) / (pc + 1e-5f);
        al = fminf(fmaxf(al, 0.f), 1.f);
        out[(size_t)NP * 3 + pt]  = density;
        out[(size_t)NP * 11 + pt] = al;
    }
}

// ---------------- launch ----------------
extern "C" void kernel_launch(void* const* d_in, const int* in_sizes, int n_in,
                              void* d_out, int out_size) {
    const float* points     = (const float*)d_in[0];
    const float* directions = (const float*)d_in[1];
    const float* deltas     = (const float*)d_in[2];
    const float* vol0       = (const float*)d_in[3];
    const float* vol1       = (const float*)d_in[4];
    const float* W0  = (const float*)d_in[5];
    const float* b0  = (const float*)d_in[6];
    const float* W1  = (const float*)d_in[7];
    const float* b1  = (const float*)d_in[8];
    const float* W2  = (const float*)d_in[9];
    const float* b2  = (const float*)d_in[10];
    const float* Wr0 = (const float*)d_in[11];
    const float* br0 = (const float*)d_in[12];
    const float* Wr1 = (const float*)d_in[13];
    const float* br1 = (const float*)d_in[14];
    const float* beta     = (const float*)d_in[15];
    const float* variance = (const float*)d_in[16];
    float* out = (float*)d_out;

    cudaFuncSetAttribute(k_forward,  cudaFuncAttributeMaxDynamicSharedMemorySize, 26880 * 4);
    cudaFuncSetAttribute(k_backward, cudaFuncAttributeMaxDynamicSharedMemorySize, 27840 * 4);
    cudaFuncSetAttribute(k_rgb,      cudaFuncAttributeMaxDynamicSharedMemorySize, 28160 * 4);

    k_transpose<<<128, 256>>>(W0, W1);
    k_sample<<<NP / 64, 64, 8320 * 4>>>(points, vol0, vol1);
    k_forward<<<NP / 64, 256, 26880 * 4>>>(points, W0, b0, W1, b1, W2, b2, out);
    k_backward<<<NP / 64, 256, 27840 * 4>>>(W2, out);
    k_rgb<<<NP / 64, 256, 28160 * 4>>>(points, directions, deltas,
                                       Wr0, br0, Wr1, br1, beta, variance, out);
}